// round 5
// baseline (speedup 1.0000x reference)
#include <cuda_runtime.h>
#include <math.h>

// Problem constants (fixed by this dataset instance)
constexpr int B = 16, P = 19248, C = 81, G = 16;
constexpr float VAR0 = 0.1f, VAR1 = 0.2f;
constexpr float POS_T = 0.5f, NEG_T = 0.4f;
constexpr int   NPR = 3;
constexpr float BBOX_ALPHA = 1.5f, CONF_ALPHA = 1.0f;

constexpr int TILE = 48;            // priors per k_conf block (48*401 == P exactly)
constexpr int CONF_THREADS = 384;   // 8 threads per prior row
constexpr int NBINS = 65536;        // top-16-bit histogram

// -------- scratch (device globals; no allocation allowed) --------
__device__ unsigned long long g_bestgt[B * G];
__device__ float              g_sl1   [B * P];
__device__ unsigned           g_lcbits[B * P];
__device__ float              g_ce    [B * P];
__device__ unsigned char      g_state [B * P];   // 0=neg, 1=pos, 2=neutral
__device__ int                g_numpos[B];
__device__ unsigned           g_hist  [B * NBINS];
__device__ int                g_hb    [B];
__device__ int                g_r     [B];
__device__ unsigned long long g_cand  [B * P];
__device__ int                g_ccnt  [B];
__device__ unsigned           g_T     [B];
__device__ int                g_cut   [B];
__device__ double             g_acc   [2];
__device__ unsigned           g_done;

// -------- kernel 0: reset (grid covers 4MB histogram) --------
__global__ void k_reset() {
    int id = blockIdx.x * 1024 + threadIdx.x;
    if (id < B * NBINS) g_hist[id] = 0u;
    if (blockIdx.x == 0) {
        int t = threadIdx.x;
        if (t < B * G) g_bestgt[t] = 0ULL;
        if (t < B)   { g_numpos[t] = 0; g_ccnt[t] = 0; }
        if (t < 2)     g_acc[t] = 0.0;
        if (t == 0)    g_done = 0u;
    }
}

// -------- kernel 1: per-GT best prior only (per-prior results recomputed later) --------
__global__ void k_match(const float4* __restrict__ priors4,
                        const float* __restrict__ gtb) {
    __shared__ float sg[G * 4];
    __shared__ float sga[G];
    __shared__ unsigned long long sbest[G];
    int b = blockIdx.y;
    int t = threadIdx.x;
    if (t < G * 4) sg[t] = gtb[b * G * 4 + t];
    if (t < G)     sbest[t] = 0ULL;
    __syncthreads();
    if (t < G)     sga[t] = (sg[t*4+2] - sg[t*4+0]) * (sg[t*4+3] - sg[t*4+1]);
    __syncthreads();

    int p = blockIdx.x * blockDim.x + t;
    if (p < P) {
        float4 pr = priors4[(size_t)b * P + p];
        float bx1 = pr.x - 0.5f * pr.z, by1 = pr.y - 0.5f * pr.w;
        float bx2 = pr.x + 0.5f * pr.z, by2 = pr.y + 0.5f * pr.w;
        float areaB = pr.z * pr.w;
        #pragma unroll
        for (int g = 0; g < G; g++) {
            float iw = fmaxf(fminf(sg[g*4+2], bx2) - fmaxf(sg[g*4+0], bx1), 0.0f);
            float ih = fmaxf(fminf(sg[g*4+3], by2) - fmaxf(sg[g*4+1], by1), 0.0f);
            float inter = iw * ih;
            float iou = inter / fmaxf(sga[g] + areaB - inter, 1e-10f);
            unsigned long long key =
                ((unsigned long long)__float_as_uint(iou) << 32) |
                (unsigned long long)(0xFFFFFFFFu - (unsigned)p);  // max iou, then min p
            atomicMax(&sbest[g], key);
        }
    }
    __syncthreads();
    if (t < G) atomicMax(&g_bestgt[b * G + t], sbest[t]);
}

// -------- kernel 2: conf loss pieces + match recompute + force-match + SL1 + hist --------
__global__ __launch_bounds__(CONF_THREADS)
void k_conf(const float* __restrict__ conf,
            const float* __restrict__ loc,
            const float* __restrict__ priors,
            const float* __restrict__ gtb,
            const int*   __restrict__ gtl) {
    __shared__ float sconf[TILE * C];          // 15552 B
    __shared__ int   sbestp[G];
    __shared__ int   slab[G];
    __shared__ float sgb[G * 4];
    __shared__ float sga[G];
    __shared__ int   s_pos[CONF_THREADS / 32];

    int b    = blockIdx.y;
    int tile = blockIdx.x;
    int t    = threadIdx.x;

    if (t < G) {
        unsigned long long key = g_bestgt[b * G + t];
        sbestp[t] = (int)(0xFFFFFFFFu - (unsigned)(key & 0xFFFFFFFFull));
        slab[t]   = gtl[b * G + t];
    }
    if (t < G * 4) sgb[t] = gtb[b * G * 4 + t];

    {
        const float4* src = (const float4*)(conf + ((size_t)b * P + (size_t)tile * TILE) * C);
        float4* dst = (float4*)sconf;
        constexpr int N4 = TILE * C / 4;   // 972
        for (int i = t; i < N4; i += CONF_THREADS) dst[i] = src[i];
    }
    __syncthreads();
    if (t < G) sga[t] = (sgb[t*4+2] - sgb[t*4+0]) * (sgb[t*4+3] - sgb[t*4+1]);
    __syncthreads();

    int row = t >> 3;           // 0..47
    int sub = t & 7;            // 0..7
    const float* srow = sconf + row * C;

    float v[11];
    #pragma unroll
    for (int i = 0; i < 11; i++) {
        int j = sub + i * 8;
        v[i] = (j < C) ? srow[j] : -1e30f;
    }
    float m = v[0];
    #pragma unroll
    for (int i = 1; i < 11; i++) m = fmaxf(m, v[i]);
    m = fmaxf(m, __shfl_xor_sync(0xffffffffu, m, 1));
    m = fmaxf(m, __shfl_xor_sync(0xffffffffu, m, 2));
    m = fmaxf(m, __shfl_xor_sync(0xffffffffu, m, 4));
    float s = 0.0f;
    #pragma unroll
    for (int i = 0; i < 11; i++) s += __expf(v[i] - m);
    s += __shfl_xor_sync(0xffffffffu, s, 1);
    s += __shfl_xor_sync(0xffffffffu, s, 2);
    s += __shfl_xor_sync(0xffffffffu, s, 4);

    bool is_pos = false;
    if (sub == 0) {
        float lse = m + logf(s);
        int p   = tile * TILE + row;
        int idx = b * P + p;
        // recompute per-prior match (bit-identical to k_match arithmetic)
        const float4 pr = *(const float4*)(priors + (size_t)idx * 4);
        float bx1 = pr.x - 0.5f * pr.z, by1 = pr.y - 0.5f * pr.w;
        float bx2 = pr.x + 0.5f * pr.z, by2 = pr.y + 0.5f * pr.w;
        float areaB = pr.z * pr.w;
        float bo = -1.0f; int bi = 0;
        #pragma unroll
        for (int g = 0; g < G; g++) {
            float iw = fmaxf(fminf(sgb[g*4+2], bx2) - fmaxf(sgb[g*4+0], bx1), 0.0f);
            float ih = fmaxf(fminf(sgb[g*4+3], by2) - fmaxf(sgb[g*4+1], by1), 0.0f);
            float inter = iw * ih;
            float iou = inter / fmaxf(sga[g] + areaB - inter, 1e-10f);
            if (iou > bo) { bo = iou; bi = g; }   // first-index argmax
        }
        // force-match (ascending g == sequential scatter, last wins)
        #pragma unroll
        for (int g = 0; g < G; g++)
            if (sbestp[g] == p) { bo = 2.0f; bi = g; }

        int lab = slab[bi];
        int conf_t = (bo < POS_T) ? ((bo < NEG_T) ? 0 : -1) : lab;
        bool pos = conf_t > 0;
        is_pos = pos;
        int tgt = pos ? conf_t : 0;
        float ce = lse - srow[tgt];
        float lc = (pos || conf_t < 0) ? 0.0f : (lse - srow[0]);
        unsigned bits = __float_as_uint(lc);      // lc >= 0: bits monotonic
        g_ce[idx]     = ce;
        g_lcbits[idx] = bits;
        g_state[idx]  = pos ? 1 : (conf_t < 0 ? 2 : 0);
        atomicAdd(&g_hist[b * NBINS + (bits >> 16)], 1u);
        float sl = 0.0f;
        if (pos) {
            const float4 ld = *(const float4*)(loc + (size_t)idx * 4);
            float gx1 = sgb[bi*4+0], gy1 = sgb[bi*4+1];
            float gx2 = sgb[bi*4+2], gy2 = sgb[bi*4+3];
            float t0 = ((gx1 + gx2) * 0.5f - pr.x) / (VAR0 * pr.z);
            float t1 = ((gy1 + gy2) * 0.5f - pr.y) / (VAR0 * pr.w);
            float t2 = logf(fmaxf((gx2 - gx1) / pr.z, 1e-8f)) / VAR1;
            float t3 = logf(fmaxf((gy2 - gy1) / pr.w, 1e-8f)) / VAR1;
            float d;
            d = ld.x - t0; sl += (fabsf(d) < 1.0f) ? 0.5f * d * d : fabsf(d) - 0.5f;
            d = ld.y - t1; sl += (fabsf(d) < 1.0f) ? 0.5f * d * d : fabsf(d) - 0.5f;
            d = ld.z - t2; sl += (fabsf(d) < 1.0f) ? 0.5f * d * d : fabsf(d) - 0.5f;
            d = ld.w - t3; sl += (fabsf(d) < 1.0f) ? 0.5f * d * d : fabsf(d) - 0.5f;
        }
        g_sl1[idx] = sl;
    }
    unsigned bal = __ballot_sync(0xffffffffu, is_pos);
    if ((t & 31) == 0) s_pos[t >> 5] = __popc(bal);
    __syncthreads();
    if (t == 0) {
        int c = 0;
        #pragma unroll
        for (int w = 0; w < CONF_THREADS / 32; w++) c += s_pos[w];
        if (c) atomicAdd(&g_numpos[b], c);
    }
}

// -------- kernel 3: boundary bin from histogram only (no data pass) --------
__global__ __launch_bounds__(1024)
void k_thresh() {
    int b = blockIdx.x;
    int t = threadIdx.x;
    __shared__ int sc[1024];
    const unsigned* h = g_hist + b * NBINS;

    int k = NPR * g_numpos[b];
    if (k > P - 1) k = P - 1;

    int local = 0;
    #pragma unroll 4
    for (int i = 0; i < 64; i++) local += (int)h[t * 64 + i];
    sc[t] = local;
    __syncthreads();
    // suffix sums over 1024 chunks: sc[t] = sum_{j>=t}
    for (int off = 1; off < 1024; off <<= 1) {
        int add = (t + off < 1024) ? sc[t + off] : 0;
        __syncthreads();
        sc[t] += add;
        __syncthreads();
    }
    // boundary chunk: above_chunk < k <= sc[c]
    int above_chunk = (t + 1 < 1024) ? sc[t + 1] : 0;
    if (above_chunk < k && k <= sc[t]) {
        int above = above_chunk;
        for (int j = 63; j >= 0; j--) {
            int cnt = (int)h[t * 64 + j];
            if (k <= above + cnt) {
                g_hb[b] = t * 64 + j;
                g_r[b]  = k - above;
                break;
            }
            above += cnt;
        }
    }
}

// -------- kernel 4: gather candidates in boundary bin --------
__global__ __launch_bounds__(1024)
void k_gather() {
    int b = blockIdx.y;
    int p = blockIdx.x * 1024 + threadIdx.x;
    if (p < P) {
        unsigned bits = g_lcbits[b * P + p];
        if ((int)(bits >> 16) == g_hb[b]) {
            int pos = atomicAdd(&g_ccnt[b], 1);
            g_cand[b * P + pos] =
                ((unsigned long long)bits << 32) |
                (unsigned long long)(0xFFFFFFFFu - (unsigned)p); // bits desc, p asc
        }
    }
}

// -------- kernel 5: exact r-th largest among candidates --------
__global__ __launch_bounds__(256)
void k_pick() {
    int b = blockIdx.x;
    int t = threadIdx.x;
    __shared__ unsigned long long stage[2048];
    const unsigned long long* cand = g_cand + b * P;
    int n = g_ccnt[b];
    int r = g_r[b];

    // each thread owns candidates t, t+256, ... ; count strictly-greater keys
    constexpr int MAXOWN = 76;  // ceil(P/256) upper bound; real n is tiny
    int cnt[4];                  // support up to 4*256=1024 candidates fast path
    unsigned long long own[4];
    int nown = 0;
    for (int i = t; i < n && nown < 4; i += 256) { own[nown] = cand[i]; cnt[nown] = 0; nown++; }
    bool big = (n > 1024);

    for (int base = 0; base < n; base += 2048) {
        int m = min(2048, n - base);
        for (int i = t; i < m; i += 256) stage[i] = cand[base + i];
        __syncthreads();
        for (int o = 0; o < nown; o++) {
            unsigned long long key = own[o];
            for (int i = 0; i < m; i++)
                if (stage[i] > key) cnt[o]++;
        }
        __syncthreads();
    }
    for (int o = 0; o < nown; o++) {
        if (cnt[o] == r - 1) {
            g_T[b]   = (unsigned)(own[o] >> 32);
            g_cut[b] = (int)(0xFFFFFFFFu - (unsigned)(own[o] & 0xFFFFFFFFull));
        }
    }
    // slow fallback for pathologically large candidate sets (> 1024)
    if (big) {
        for (int i = t + 1024; i < n; i += 256) {
            unsigned long long key = cand[i];
            int c = 0;
            for (int j = 0; j < n; j++) if (cand[j] > key) c++;
            if (c == r - 1) {
                g_T[b]   = (unsigned)(key >> 32);
                g_cut[b] = (int)(0xFFFFFFFFu - (unsigned)(key & 0xFFFFFFFFull));
            }
        }
    }
    (void)MAXOWN;
}

// -------- kernel 6: final masked sums + output --------
__global__ __launch_bounds__(256)
void k_final(float* __restrict__ out) {
    int b = blockIdx.y;
    int p = blockIdx.x * 256 + threadIdx.x;
    float cB = 0.0f, cC = 0.0f;
    if (p < P) {
        int idx = b * P + p;
        int st = g_state[idx];
        unsigned bits = g_lcbits[idx];
        unsigned T = g_T[b];
        int cut = g_cut[b];
        bool neg = (st == 0) && (bits > T || (bits == T && p <= cut));
        bool pos = (st == 1);
        if (pos) cB = g_sl1[idx] / (float)max(g_numpos[b], 1);
        if (pos || neg) cC = g_ce[idx];
    }
    #pragma unroll
    for (int o = 16; o > 0; o >>= 1) {
        cB += __shfl_xor_sync(0xffffffffu, cB, o);
        cC += __shfl_xor_sync(0xffffffffu, cC, o);
    }
    __shared__ float sB[8], sC[8];
    int w = threadIdx.x >> 5;
    if ((threadIdx.x & 31) == 0) { sB[w] = cB; sC[w] = cC; }
    __syncthreads();
    if (threadIdx.x == 0) {
        float tB = 0.0f, tC = 0.0f;
        #pragma unroll
        for (int i = 0; i < 8; i++) { tB += sB[i]; tC += sC[i]; }
        if (tB != 0.0f) atomicAdd(&g_acc[0], (double)tB);
        if (tC != 0.0f) atomicAdd(&g_acc[1], (double)tC);
        __threadfence();
        unsigned old = atomicAdd(&g_done, 1u);
        if (old == gridDim.x * gridDim.y - 1) {
            out[0] = (float)(g_acc[0] * (double)BBOX_ALPHA / (double)B);
            out[1] = (float)(g_acc[1] * (double)CONF_ALPHA / (double)B);
        }
    }
}

extern "C" void kernel_launch(void* const* d_in, const int* in_sizes, int n_in,
                              void* d_out, int out_size) {
    const float* loc    = (const float*)d_in[0];
    const float* conf   = (const float*)d_in[1];
    const float* priors = (const float*)d_in[2];
    const float* gtb    = (const float*)d_in[3];
    const int*   gtl    = (const int*)d_in[4];
    float* out = (float*)d_out;

    k_reset<<<(B * NBINS + 1023) / 1024, 1024>>>();
    {
        dim3 grid((P + 255) / 256, B);
        k_match<<<grid, 256>>>((const float4*)priors, gtb);
    }
    {
        dim3 grid(P / TILE, B);   // 401 x 16
        k_conf<<<grid, CONF_THREADS>>>(conf, loc, priors, gtb, gtl);
    }
    k_thresh<<<B, 1024>>>();
    {
        dim3 grid((P + 1023) / 1024, B);
        k_gather<<<grid, 1024>>>();
    }
    k_pick<<<B, 256>>>();
    {
        dim3 grid((P + 255) / 256, B);
        k_final<<<grid, 256>>>(out);
    }
}